// round 7
// baseline (speedup 1.0000x reference)
#include <cuda_runtime.h>
#include <cuda_bf16.h>
#include <math.h>
#include <stdint.h>

#define B_ROWS 8192
#define D_DIM  512
#define EPS_PD 1e-6f
#define MARGIN 0.3f

// GEMM tiling: CTA 128x256, 8 warps (2x4), warp 64x64, BK=64
#define BM     128
#define BN     256
#define BK     64
#define NCHUNK (D_DIM / BK)          // 8
#define NTM    (B_ROWS / BM)         // 64
#define NTN    (B_ROWS / BN)         // 32

// SMEM layout (dynamic)
#define A_BYTES   (BM * 128)         // 16384
#define B_BYTES   (BN * 128)         // 32768
#define OFF_A0    0
#define OFF_A1    (A_BYTES)                    // 16384
#define OFF_B0    (2 * A_BYTES)                // 32768
#define OFF_B1    (2 * A_BYTES + B_BYTES)      // 65536
#define OFF_CJ    (2 * A_BYTES + 2 * B_BYTES)  // 98304 (256 floats)
#define OFF_RMIN  (OFF_CJ + BN * 4)            // 99328 (128 x 4 floats)
#define SMEM_TOTAL (OFF_RMIN + 128 * 4 * 4)    // 101376

// ---------------- device scratch ----------------
__device__ __align__(16) __nv_bfloat16 g_anb[B_ROWS * D_DIM];
__device__ __align__(16) __nv_bfloat16 g_pnb[B_ROWS * D_DIM];
__device__ float g_sa[B_ROWS], g_sa2[B_ROWS], g_posd2[B_ROWS], g_cj[B_ROWS];
__device__ float g_pmin[NTN][B_ROWS];
__device__ float g_bsum[32];

// ---------------- helpers ----------------
__device__ __forceinline__ uint32_t smem_u32(const void* p) {
    uint32_t a;
    asm("{ .reg .u64 t; cvta.to.shared.u64 t, %1; cvt.u32.u64 %0, t; }"
        : "=r"(a) : "l"(p));
    return a;
}
__device__ __forceinline__ uint32_t swz(uint32_t row, uint32_t colByte) {
    return row * 128u + (colByte ^ ((row & 7u) << 4));
}

#define CP_ASYNC16(dst, src) \
    asm volatile("cp.async.cg.shared.global [%0], [%1], 16;" :: "r"(dst), "l"(src) : "memory")
#define CP_COMMIT() asm volatile("cp.async.commit_group;" ::: "memory")

__device__ __forceinline__ void ldsm_x4(uint32_t addr, uint32_t& r0, uint32_t& r1,
                                        uint32_t& r2, uint32_t& r3) {
    asm volatile("ldmatrix.sync.aligned.m8n8.x4.shared.b16 {%0,%1,%2,%3}, [%4];"
                 : "=r"(r0), "=r"(r1), "=r"(r2), "=r"(r3) : "r"(addr));
}
__device__ __forceinline__ void mma16816(float& c0, float& c1, float& c2, float& c3,
                                         uint32_t a0, uint32_t a1, uint32_t a2, uint32_t a3,
                                         uint32_t b0, uint32_t b1) {
    asm volatile("mma.sync.aligned.m16n8k16.row.col.f32.bf16.bf16.f32 "
                 "{%0,%1,%2,%3}, {%4,%5,%6,%7}, {%8,%9}, {%0,%1,%2,%3};"
                 : "+f"(c0), "+f"(c1), "+f"(c2), "+f"(c3)
                 : "r"(a0), "r"(a1), "r"(a2), "r"(a3), "r"(b0), "r"(b1));
}

__device__ __forceinline__ float warpReduceSum(float v) {
    #pragma unroll
    for (int o = 16; o >= 1; o >>= 1) v += __shfl_xor_sync(0xffffffffu, v, o);
    return v;
}
__device__ __forceinline__ float blockReduceSum(float v, float* sm, int nwarp) {
    v = warpReduceSum(v);
    int w = threadIdx.x >> 5;
    if ((threadIdx.x & 31) == 0) sm[w] = v;
    __syncthreads();
    float r = 0.0f;
    for (int i = 0; i < nwarp; i++) r += sm[i];
    __syncthreads();
    return r;
}

// ---------------- K1: warp-per-row normalize -> bf16 + scalars ----------------
__global__ void normalize_kernel(const float* __restrict__ x) {
    int warp = (blockIdx.x * blockDim.x + threadIdx.x) >> 5;   // row id
    int lane = threadIdx.x & 31;
    if (warp >= B_ROWS) return;

    const float4* xa = reinterpret_cast<const float4*>(x + (size_t)warp * 2 * D_DIM);
    const float4* xp = xa + D_DIM / 4;

    float4 a[4], p[4];
    float ssa = 0.0f, ssp = 0.0f;
    #pragma unroll
    for (int q = 0; q < 4; q++) {
        a[q] = xa[lane + 32 * q];
        p[q] = xp[lane + 32 * q];
        ssa += a[q].x*a[q].x + a[q].y*a[q].y + a[q].z*a[q].z + a[q].w*a[q].w;
        ssp += p[q].x*p[q].x + p[q].y*p[q].y + p[q].z*p[q].z + p[q].w*p[q].w;
    }
    ssa = warpReduceSum(ssa);
    ssp = warpReduceSum(ssp);
    float inva = 1.0f / fmaxf(sqrtf(ssa), 1e-12f);
    float invp = 1.0f / fmaxf(sqrtf(ssp), 1e-12f);

    uint2* oa = reinterpret_cast<uint2*>(g_anb + (size_t)warp * D_DIM);
    uint2* op = reinterpret_cast<uint2*>(g_pnb + (size_t)warp * D_DIM);
    float s1a = 0.0f, s1p = 0.0f, dotv = 0.0f;
    #pragma unroll
    for (int q = 0; q < 4; q++) {
        a[q].x *= inva; a[q].y *= inva; a[q].z *= inva; a[q].w *= inva;
        p[q].x *= invp; p[q].y *= invp; p[q].z *= invp; p[q].w *= invp;
        s1a  += a[q].x + a[q].y + a[q].z + a[q].w;
        s1p  += p[q].x + p[q].y + p[q].z + p[q].w;
        dotv += a[q].x*p[q].x + a[q].y*p[q].y + a[q].z*p[q].z + a[q].w*p[q].w;
        __nv_bfloat162 a0 = __floats2bfloat162_rn(a[q].x, a[q].y);
        __nv_bfloat162 a1 = __floats2bfloat162_rn(a[q].z, a[q].w);
        __nv_bfloat162 p0 = __floats2bfloat162_rn(p[q].x, p[q].y);
        __nv_bfloat162 p1 = __floats2bfloat162_rn(p[q].z, p[q].w);
        uint2 ua, up;
        ua.x = *reinterpret_cast<uint32_t*>(&a0); ua.y = *reinterpret_cast<uint32_t*>(&a1);
        up.x = *reinterpret_cast<uint32_t*>(&p0); up.y = *reinterpret_cast<uint32_t*>(&p1);
        oa[lane + 32 * q] = ua;
        op[lane + 32 * q] = up;
    }
    s1a  = warpReduceSum(s1a);
    s1p  = warpReduceSum(s1p);
    dotv = warpReduceSum(dotv);
    if (lane == 0) {
        float s2a = ssa * inva * inva;     // == sum(a_norm^2) to fp32 rounding
        float s2p = ssp * invp * invp;
        g_sa[warp]  = s1a;
        g_sa2[warp] = s2a;
        g_cj[warp]  = s2p - 2.0f * EPS_PD * s1p;
        g_posd2[warp] = s2a + s2p - 2.0f * dotv
                      + 2.0f * EPS_PD * (s1a - s1p)
                      + (float)D_DIM * EPS_PD * EPS_PD;
    }
}

// ---------------- K2: bf16 mma.sync GEMM + fused row-min ----------------
// blockIdx.x = N tile (fast -> consecutive CTAs share A rows in L2), blockIdx.y = M tile
__global__ __launch_bounds__(256, 1) void gemm_min_kernel() {
    extern __shared__ char smem[];
    const uint32_t sb = smem_u32(smem);
    const int t    = threadIdx.x;          // 256 threads, 8 warps
    const int wid  = t >> 5;
    const int lane = t & 31;
    const int wm   = wid >> 2;             // 0..1 : M half (64 rows)
    const int wn   = wid & 3;              // 0..3 : N quarter (64 cols)
    const int row0 = blockIdx.y * BM;
    const int col0 = blockIdx.x * BN;

    reinterpret_cast<float*>(smem + OFF_CJ)[t] = g_cj[col0 + t];

    const char* Agc = reinterpret_cast<const char*>(g_anb);
    const char* Bgc = reinterpret_cast<const char*>(g_pnb);

    // lane-fixed ldmatrix base offsets (ks=0); +32B per k16 step
    uint32_t aOff[4];
    {
        int tIdx = lane >> 3, r = lane & 7;
        #pragma unroll
        for (int mi = 0; mi < 4; mi++) {
            uint32_t m  = (uint32_t)(wm * 64 + mi * 16 + (tIdx & 1) * 8 + r);
            uint32_t cb = (uint32_t)((tIdx >> 1) * 16);
            aOff[mi] = swz(m, cb);
        }
    }
    uint32_t bOff[4];
    {
        int tIdx = lane >> 3, r = lane & 7;
        #pragma unroll
        for (int nt2 = 0; nt2 < 4; nt2++) {
            uint32_t n  = (uint32_t)(wn * 64 + nt2 * 16 + (tIdx >> 1) * 8 + r);
            uint32_t cb = (uint32_t)((tIdx & 1) * 16);
            bOff[nt2] = swz(n, cb);
        }
    }

    float acc[4][8][4];
    #pragma unroll
    for (int mi = 0; mi < 4; mi++)
        #pragma unroll
        for (int ni = 0; ni < 8; ni++)
            #pragma unroll
            for (int k = 0; k < 4; k++) acc[mi][ni][k] = 0.0f;

    // prefetch chunk 0: A 1024 x16B (4/thread), B 2048 x16B (8/thread)
    {
        #pragma unroll
        for (int j = 0; j < 4; j++) {
            int i = t + j * 256;
            int r = i >> 3, s = i & 7;
            CP_ASYNC16(sb + OFF_A0 + swz((uint32_t)r, (uint32_t)(s * 16)),
                       Agc + ((size_t)(row0 + r) * D_DIM + s * 8) * 2);
        }
        #pragma unroll
        for (int j = 0; j < 8; j++) {
            int i = t + j * 256;
            int r = i >> 3, s = i & 7;
            CP_ASYNC16(sb + OFF_B0 + swz((uint32_t)r, (uint32_t)(s * 16)),
                       Bgc + ((size_t)(col0 + r) * D_DIM + s * 8) * 2);
        }
        CP_COMMIT();
    }

    for (int c = 0; c < NCHUNK; c++) {
        if (c + 1 < NCHUNK) {
            uint32_t abase = sb + (((c + 1) & 1) ? OFF_A1 : OFF_A0);
            uint32_t bbase = sb + (((c + 1) & 1) ? OFF_B1 : OFF_B0);
            int kq = (c + 1) * BK;
            #pragma unroll
            for (int j = 0; j < 4; j++) {
                int i = t + j * 256;
                int r = i >> 3, s = i & 7;
                CP_ASYNC16(abase + swz((uint32_t)r, (uint32_t)(s * 16)),
                           Agc + ((size_t)(row0 + r) * D_DIM + kq + s * 8) * 2);
            }
            #pragma unroll
            for (int j = 0; j < 8; j++) {
                int i = t + j * 256;
                int r = i >> 3, s = i & 7;
                CP_ASYNC16(bbase + swz((uint32_t)r, (uint32_t)(s * 16)),
                           Bgc + ((size_t)(col0 + r) * D_DIM + kq + s * 8) * 2);
            }
            CP_COMMIT();
            asm volatile("cp.async.wait_group 1;" ::: "memory");
        } else {
            asm volatile("cp.async.wait_group 0;" ::: "memory");
        }
        __syncthreads();

        const uint32_t aB = sb + ((c & 1) ? OFF_A1 : OFF_A0);
        const uint32_t bB = sb + ((c & 1) ? OFF_B1 : OFF_B0);

        #pragma unroll
        for (int ks = 0; ks < 4; ks++) {
            uint32_t af[4][4];
            uint32_t bf[8][2];
            #pragma unroll
            for (int mi = 0; mi < 4; mi++)
                ldsm_x4(aB + aOff[mi] + ks * 32,
                        af[mi][0], af[mi][1], af[mi][2], af[mi][3]);
            #pragma unroll
            for (int nt2 = 0; nt2 < 4; nt2++) {
                uint32_t r0, r1, r2, r3;
                ldsm_x4(bB + bOff[nt2] + ks * 32, r0, r1, r2, r3);
                bf[nt2 * 2][0] = r0;     bf[nt2 * 2][1] = r1;
                bf[nt2 * 2 + 1][0] = r2; bf[nt2 * 2 + 1][1] = r3;
            }
            #pragma unroll
            for (int mi = 0; mi < 4; mi++)
                #pragma unroll
                for (int ni = 0; ni < 8; ni++)
                    mma16816(acc[mi][ni][0], acc[mi][ni][1], acc[mi][ni][2], acc[mi][ni][3],
                             af[mi][0], af[mi][1], af[mi][2], af[mi][3],
                             bf[ni][0], bf[ni][1]);
        }
        __syncthreads();
    }

    // epilogue: val = cj[j] - 2*dot, diagonal masked, fused row-min
    const float* cjs = reinterpret_cast<const float*>(smem + OFF_CJ);
    float* rminS = reinterpret_cast<float*>(smem + OFF_RMIN);   // [128][4]
    const int g  = lane >> 2;
    const int t2 = (lane & 3) * 2;

    #pragma unroll
    for (int mi = 0; mi < 4; mi++) {
        float rlow = INFINITY, rhigh = INFINITY;
        const int rowLow  = row0 + wm * 64 + mi * 16 + g;
        const int rowHigh = rowLow + 8;
        #pragma unroll
        for (int ni = 0; ni < 8; ni++) {
            #pragma unroll
            for (int d = 0; d < 2; d++) {
                int cl = wn * 64 + ni * 8 + t2 + d;
                int cg = col0 + cl;
                float cjv = cjs[cl];
                float vl = cjv - 2.0f * acc[mi][ni][d];
                float vh = cjv - 2.0f * acc[mi][ni][2 + d];
                if (cg != rowLow)  rlow  = fminf(rlow, vl);
                if (cg != rowHigh) rhigh = fminf(rhigh, vh);
            }
        }
        #pragma unroll
        for (int o = 1; o <= 2; o <<= 1) {
            rlow  = fminf(rlow,  __shfl_xor_sync(0xffffffffu, rlow, o));
            rhigh = fminf(rhigh, __shfl_xor_sync(0xffffffffu, rhigh, o));
        }
        if ((lane & 3) == 0) {
            rminS[(wm * 64 + mi * 16 + g) * 4 + wn]     = rlow;
            rminS[(wm * 64 + mi * 16 + 8 + g) * 4 + wn] = rhigh;
        }
    }
    __syncthreads();
    if (t < 128) {
        float m = fminf(fminf(rminS[t * 4 + 0], rminS[t * 4 + 1]),
                        fminf(rminS[t * 4 + 2], rminS[t * 4 + 3]));
        g_pmin[blockIdx.x][row0 + t] = m;
    }
}

// ---------------- K3/K4: finalize ----------------
__global__ void finalize1_kernel() {
    __shared__ float sm[8];
    int i = blockIdx.x * 256 + threadIdx.x;       // 32 x 256 = 8192
    float m = INFINITY;
    #pragma unroll
    for (int s = 0; s < NTN; s++) m = fminf(m, g_pmin[s][i]);
    float negd2 = g_sa2[i] + 2.0f * EPS_PD * g_sa[i]
                + (float)D_DIM * EPS_PD * EPS_PD + m;
    float v = fmaxf(g_posd2[i] - negd2 + MARGIN, 0.0f);
    v = blockReduceSum(v, sm, 8);
    if (threadIdx.x == 0) g_bsum[blockIdx.x] = v;
}

__global__ void finalize2_kernel(float* __restrict__ out) {
    float v = g_bsum[threadIdx.x];                 // 32 threads
    #pragma unroll
    for (int o = 16; o >= 1; o >>= 1) v += __shfl_xor_sync(0xffffffffu, v, o);
    if (threadIdx.x == 0) out[0] = v / (float)B_ROWS;
}

// ---------------- launch ----------------
extern "C" void kernel_launch(void* const* d_in, const int* in_sizes, int n_in,
                              void* d_out, int out_size) {
    const float* x = (const float*)d_in[0];
    float* out = (float*)d_out;

    cudaFuncSetAttribute(gemm_min_kernel,
                         cudaFuncAttributeMaxDynamicSharedMemorySize, SMEM_TOTAL);

    normalize_kernel<<<B_ROWS / 8, 256>>>(x);
    gemm_min_kernel<<<dim3(NTN, NTM), 256, SMEM_TOTAL>>>();
    finalize1_kernel<<<32, 256>>>();
    finalize2_kernel<<<1, 32>>>(out);
}

// round 8
// speedup vs baseline: 1.0987x; 1.0987x over previous
#include <cuda_runtime.h>
#include <cuda_bf16.h>
#include <math.h>
#include <stdint.h>

#define B_ROWS 8192
#define D_DIM  512
#define EPS_PD 1e-6f
#define MARGIN 0.3f

// GEMM tiling: CTA 128x128, 8 warps (2x4), warp 64x32, BK=64, 3-stage pipeline
#define BT     128
#define BK     64
#define NCHUNK (D_DIM / BK)          // 8
#define NT     (B_ROWS / BT)         // 64

// SMEM: 3 A bufs, 3 B bufs (each 128 rows x 128B), cj, rmin
#define TILE_BYTES (BT * 128)        // 16384
#define OFF_A(i)  ((i) * TILE_BYTES)
#define OFF_B(i)  ((3 + (i)) * TILE_BYTES)
#define OFF_CJ    (6 * TILE_BYTES)              // 98304 (128 floats)
#define OFF_RMIN  (OFF_CJ + 512)                // 98816 (128 x 4 floats)
#define SMEM_TOTAL (OFF_RMIN + 128 * 4 * 4)     // 100864

// ---------------- device scratch ----------------
__device__ __align__(16) __nv_bfloat16 g_anb[B_ROWS * D_DIM];
__device__ __align__(16) __nv_bfloat16 g_pnb[B_ROWS * D_DIM];
__device__ float g_sa[B_ROWS], g_sa2[B_ROWS], g_posd2[B_ROWS], g_cj[B_ROWS];
__device__ float g_pmin[NT][B_ROWS];
__device__ float g_bsum[32];

// ---------------- helpers ----------------
__device__ __forceinline__ uint32_t smem_u32(const void* p) {
    uint32_t a;
    asm("{ .reg .u64 t; cvta.to.shared.u64 t, %1; cvt.u32.u64 %0, t; }"
        : "=r"(a) : "l"(p));
    return a;
}
__device__ __forceinline__ uint32_t swz(uint32_t row, uint32_t colByte) {
    return row * 128u + (colByte ^ ((row & 7u) << 4));
}

#define CP_ASYNC16(dst, src) \
    asm volatile("cp.async.cg.shared.global [%0], [%1], 16;" :: "r"(dst), "l"(src) : "memory")
#define CP_COMMIT() asm volatile("cp.async.commit_group;" ::: "memory")

__device__ __forceinline__ void ldsm_x4(uint32_t addr, uint32_t& r0, uint32_t& r1,
                                        uint32_t& r2, uint32_t& r3) {
    asm volatile("ldmatrix.sync.aligned.m8n8.x4.shared.b16 {%0,%1,%2,%3}, [%4];"
                 : "=r"(r0), "=r"(r1), "=r"(r2), "=r"(r3) : "r"(addr));
}
__device__ __forceinline__ void mma16816(float& c0, float& c1, float& c2, float& c3,
                                         uint32_t a0, uint32_t a1, uint32_t a2, uint32_t a3,
                                         uint32_t b0, uint32_t b1) {
    asm volatile("mma.sync.aligned.m16n8k16.row.col.f32.bf16.bf16.f32 "
                 "{%0,%1,%2,%3}, {%4,%5,%6,%7}, {%8,%9}, {%0,%1,%2,%3};"
                 : "+f"(c0), "+f"(c1), "+f"(c2), "+f"(c3)
                 : "r"(a0), "r"(a1), "r"(a2), "r"(a3), "r"(b0), "r"(b1));
}

__device__ __forceinline__ float warpReduceSum(float v) {
    #pragma unroll
    for (int o = 16; o >= 1; o >>= 1) v += __shfl_xor_sync(0xffffffffu, v, o);
    return v;
}
__device__ __forceinline__ float blockReduceSum(float v, float* sm, int nwarp) {
    v = warpReduceSum(v);
    int w = threadIdx.x >> 5;
    if ((threadIdx.x & 31) == 0) sm[w] = v;
    __syncthreads();
    float r = 0.0f;
    for (int i = 0; i < nwarp; i++) r += sm[i];
    __syncthreads();
    return r;
}

// ---------------- K1: warp-per-row normalize -> bf16 + scalars (exact sums) ----
__global__ void normalize_kernel(const float* __restrict__ x) {
    int warp = (blockIdx.x * blockDim.x + threadIdx.x) >> 5;   // row id
    int lane = threadIdx.x & 31;
    if (warp >= B_ROWS) return;

    const float4* xa = reinterpret_cast<const float4*>(x + (size_t)warp * 2 * D_DIM);
    const float4* xp = xa + D_DIM / 4;

    float4 a[4], p[4];
    float ssa = 0.0f, ssp = 0.0f;
    #pragma unroll
    for (int q = 0; q < 4; q++) {
        a[q] = xa[lane + 32 * q];
        p[q] = xp[lane + 32 * q];
        ssa += a[q].x*a[q].x + a[q].y*a[q].y + a[q].z*a[q].z + a[q].w*a[q].w;
        ssp += p[q].x*p[q].x + p[q].y*p[q].y + p[q].z*p[q].z + p[q].w*p[q].w;
    }
    ssa = warpReduceSum(ssa);
    ssp = warpReduceSum(ssp);
    float inva = 1.0f / fmaxf(sqrtf(ssa), 1e-12f);
    float invp = 1.0f / fmaxf(sqrtf(ssp), 1e-12f);

    uint2* oa = reinterpret_cast<uint2*>(g_anb + (size_t)warp * D_DIM);
    uint2* op = reinterpret_cast<uint2*>(g_pnb + (size_t)warp * D_DIM);
    float s1a = 0.0f, s1p = 0.0f, dotv = 0.0f, s2a = 0.0f, s2p = 0.0f;
    #pragma unroll
    for (int q = 0; q < 4; q++) {
        a[q].x *= inva; a[q].y *= inva; a[q].z *= inva; a[q].w *= inva;
        p[q].x *= invp; p[q].y *= invp; p[q].z *= invp; p[q].w *= invp;
        s1a  += a[q].x + a[q].y + a[q].z + a[q].w;
        s1p  += p[q].x + p[q].y + p[q].z + p[q].w;
        s2a  += a[q].x*a[q].x + a[q].y*a[q].y + a[q].z*a[q].z + a[q].w*a[q].w;
        s2p  += p[q].x*p[q].x + p[q].y*p[q].y + p[q].z*p[q].z + p[q].w*p[q].w;
        dotv += a[q].x*p[q].x + a[q].y*p[q].y + a[q].z*p[q].z + a[q].w*p[q].w;
        __nv_bfloat162 a0 = __floats2bfloat162_rn(a[q].x, a[q].y);
        __nv_bfloat162 a1 = __floats2bfloat162_rn(a[q].z, a[q].w);
        __nv_bfloat162 p0 = __floats2bfloat162_rn(p[q].x, p[q].y);
        __nv_bfloat162 p1 = __floats2bfloat162_rn(p[q].z, p[q].w);
        uint2 ua, up;
        ua.x = *reinterpret_cast<uint32_t*>(&a0); ua.y = *reinterpret_cast<uint32_t*>(&a1);
        up.x = *reinterpret_cast<uint32_t*>(&p0); up.y = *reinterpret_cast<uint32_t*>(&p1);
        oa[lane + 32 * q] = ua;
        op[lane + 32 * q] = up;
    }
    s1a  = warpReduceSum(s1a);
    s1p  = warpReduceSum(s1p);
    s2a  = warpReduceSum(s2a);
    s2p  = warpReduceSum(s2p);
    dotv = warpReduceSum(dotv);
    if (lane == 0) {
        g_sa[warp]  = s1a;
        g_sa2[warp] = s2a;
        g_cj[warp]  = s2p - 2.0f * EPS_PD * s1p;
        g_posd2[warp] = s2a + s2p - 2.0f * dotv
                      + 2.0f * EPS_PD * (s1a - s1p)
                      + (float)D_DIM * EPS_PD * EPS_PD;
    }
}

// ---------------- K2: bf16 mma.sync GEMM + fused row-min (3-stage) ----------
// blockIdx.x = N tile (fast -> consecutive CTAs share A rows in L2), blockIdx.y = M tile
__global__ __launch_bounds__(256, 2) void gemm_min_kernel() {
    extern __shared__ char smem[];
    const uint32_t sb = smem_u32(smem);
    const int t    = threadIdx.x;          // 256 threads, 8 warps
    const int wid  = t >> 5;
    const int lane = t & 31;
    const int wm   = wid >> 2;             // 0..1 : M half
    const int wn   = wid & 3;              // 0..3 : N quarter
    const int row0 = blockIdx.y * BT;
    const int col0 = blockIdx.x * BT;

    if (t < 128) reinterpret_cast<float*>(smem + OFF_CJ)[t] = g_cj[col0 + t];

    const char* Agc = reinterpret_cast<const char*>(g_anb);
    const char* Bgc = reinterpret_cast<const char*>(g_pnb);

    // per-thread cp.async coordinates (same for every chunk)
    const int ldR = t >> 1;                       // 0..127
    const int ldS = (t & 1) * 4;                  // 0 or 4 (16B quads: 2 per thread x4 iters)
    // we use the original mapping: 1024 quads, 4 per thread
    // lane-fixed ldmatrix base offsets (ks=0); +32B per k16 step
    uint32_t aOff[4];
    {
        int tIdx = lane >> 3, r = lane & 7;
        #pragma unroll
        for (int mi = 0; mi < 4; mi++) {
            uint32_t m  = (uint32_t)(wm * 64 + mi * 16 + (tIdx & 1) * 8 + r);
            uint32_t cb = (uint32_t)((tIdx >> 1) * 16);
            aOff[mi] = swz(m, cb);
        }
    }
    uint32_t bOff[2];
    {
        int tIdx = lane >> 3, r = lane & 7;
        #pragma unroll
        for (int nt2 = 0; nt2 < 2; nt2++) {
            uint32_t n  = (uint32_t)(wn * 32 + nt2 * 16 + (tIdx >> 1) * 8 + r);
            uint32_t cb = (uint32_t)((tIdx & 1) * 16);
            bOff[nt2] = swz(n, cb);
        }
    }
    (void)ldR; (void)ldS;

    float acc[4][4][4];
    #pragma unroll
    for (int mi = 0; mi < 4; mi++)
        #pragma unroll
        for (int ni = 0; ni < 4; ni++)
            #pragma unroll
            for (int k = 0; k < 4; k++) acc[mi][ni][k] = 0.0f;

    // prefetch chunks 0 and 1 (one commit group per chunk)
    #pragma unroll
    for (int pc = 0; pc < 2; pc++) {
        uint32_t abase = sb + OFF_A(pc);
        uint32_t bbase = sb + OFF_B(pc);
        int kq = pc * BK;
        #pragma unroll
        for (int j = 0; j < 4; j++) {
            int i = t + j * 256;
            int r = i >> 3, s = i & 7;
            CP_ASYNC16(abase + swz((uint32_t)r, (uint32_t)(s * 16)),
                       Agc + ((size_t)(row0 + r) * D_DIM + kq + s * 8) * 2);
        }
        #pragma unroll
        for (int j = 0; j < 4; j++) {
            int i = t + j * 256;
            int r = i >> 3, s = i & 7;
            CP_ASYNC16(bbase + swz((uint32_t)r, (uint32_t)(s * 16)),
                       Bgc + ((size_t)(col0 + r) * D_DIM + kq + s * 8) * 2);
        }
        CP_COMMIT();
    }

    #pragma unroll 1
    for (int c = 0; c < NCHUNK; c++) {
        // wait for chunk c (allow 1 younger group in flight), then one sync
        if (c < NCHUNK - 1) {
            asm volatile("cp.async.wait_group 1;" ::: "memory");
        } else {
            asm volatile("cp.async.wait_group 0;" ::: "memory");
        }
        __syncthreads();

        // issue chunk c+2 into buf (c+2)%3 (free: == (c-1)%3, all warps past it)
        if (c + 2 < NCHUNK) {
            int nb = (c + 2) % 3;
            uint32_t abase = sb + OFF_A(nb);
            uint32_t bbase = sb + OFF_B(nb);
            int kq = (c + 2) * BK;
            #pragma unroll
            for (int j = 0; j < 4; j++) {
                int i = t + j * 256;
                int r = i >> 3, s = i & 7;
                CP_ASYNC16(abase + swz((uint32_t)r, (uint32_t)(s * 16)),
                           Agc + ((size_t)(row0 + r) * D_DIM + kq + s * 8) * 2);
            }
            #pragma unroll
            for (int j = 0; j < 4; j++) {
                int i = t + j * 256;
                int r = i >> 3, s = i & 7;
                CP_ASYNC16(bbase + swz((uint32_t)r, (uint32_t)(s * 16)),
                           Bgc + ((size_t)(col0 + r) * D_DIM + kq + s * 8) * 2);
            }
            CP_COMMIT();
        }

        const uint32_t aB = sb + OFF_A(c % 3);
        const uint32_t bB = sb + OFF_B(c % 3);

        #pragma unroll
        for (int ks = 0; ks < 4; ks++) {
            uint32_t af[4][4];
            uint32_t bf[4][2];
            #pragma unroll
            for (int mi = 0; mi < 4; mi++)
                ldsm_x4(aB + aOff[mi] + ks * 32,
                        af[mi][0], af[mi][1], af[mi][2], af[mi][3]);
            #pragma unroll
            for (int nt2 = 0; nt2 < 2; nt2++) {
                uint32_t r0, r1, r2, r3;
                ldsm_x4(bB + bOff[nt2] + ks * 32, r0, r1, r2, r3);
                bf[nt2 * 2][0] = r0;     bf[nt2 * 2][1] = r1;
                bf[nt2 * 2 + 1][0] = r2; bf[nt2 * 2 + 1][1] = r3;
            }
            #pragma unroll
            for (int mi = 0; mi < 4; mi++)
                #pragma unroll
                for (int ni = 0; ni < 4; ni++)
                    mma16816(acc[mi][ni][0], acc[mi][ni][1], acc[mi][ni][2], acc[mi][ni][3],
                             af[mi][0], af[mi][1], af[mi][2], af[mi][3],
                             bf[ni][0], bf[ni][1]);
        }
    }

    // epilogue: val = cj[j] - 2*dot, diagonal masked, fused row-min
    const float* cjs = reinterpret_cast<const float*>(smem + OFF_CJ);
    float* rminS = reinterpret_cast<float*>(smem + OFF_RMIN);   // [128][4]
    const int g  = lane >> 2;
    const int t2 = (lane & 3) * 2;

    #pragma unroll
    for (int mi = 0; mi < 4; mi++) {
        float rlow = INFINITY, rhigh = INFINITY;
        const int rowLow  = row0 + wm * 64 + mi * 16 + g;
        const int rowHigh = rowLow + 8;
        #pragma unroll
        for (int ni = 0; ni < 4; ni++) {
            #pragma unroll
            for (int d = 0; d < 2; d++) {
                int cl = wn * 32 + ni * 8 + t2 + d;
                int cg = col0 + cl;
                float cjv = cjs[cl];
                float vl = cjv - 2.0f * acc[mi][ni][d];
                float vh = cjv - 2.0f * acc[mi][ni][2 + d];
                if (cg != rowLow)  rlow  = fminf(rlow, vl);
                if (cg != rowHigh) rhigh = fminf(rhigh, vh);
            }
        }
        #pragma unroll
        for (int o = 1; o <= 2; o <<= 1) {
            rlow  = fminf(rlow,  __shfl_xor_sync(0xffffffffu, rlow, o));
            rhigh = fminf(rhigh, __shfl_xor_sync(0xffffffffu, rhigh, o));
        }
        if ((lane & 3) == 0) {
            rminS[(wm * 64 + mi * 16 + g) * 4 + wn]     = rlow;
            rminS[(wm * 64 + mi * 16 + 8 + g) * 4 + wn] = rhigh;
        }
    }
    __syncthreads();
    if (t < 128) {
        float m = fminf(fminf(rminS[t * 4 + 0], rminS[t * 4 + 1]),
                        fminf(rminS[t * 4 + 2], rminS[t * 4 + 3]));
        g_pmin[blockIdx.x][row0 + t] = m;
    }
}

// ---------------- K3/K4: finalize ----------------
__global__ void finalize1_kernel() {
    __shared__ float sm[8];
    int i = blockIdx.x * 256 + threadIdx.x;       // 32 x 256 = 8192
    float m = INFINITY;
    #pragma unroll
    for (int s = 0; s < NT; s++) m = fminf(m, g_pmin[s][i]);
    float negd2 = g_sa2[i] + 2.0f * EPS_PD * g_sa[i]
                + (float)D_DIM * EPS_PD * EPS_PD + m;
    float v = fmaxf(g_posd2[i] - negd2 + MARGIN, 0.0f);
    v = blockReduceSum(v, sm, 8);
    if (threadIdx.x == 0) g_bsum[blockIdx.x] = v;
}

__global__ void finalize2_kernel(float* __restrict__ out) {
    float v = g_bsum[threadIdx.x];                 // 32 threads
    #pragma unroll
    for (int o = 16; o >= 1; o >>= 1) v += __shfl_xor_sync(0xffffffffu, v, o);
    if (threadIdx.x == 0) out[0] = v / (float)B_ROWS;
}

// ---------------- launch ----------------
extern "C" void kernel_launch(void* const* d_in, const int* in_sizes, int n_in,
                              void* d_out, int out_size) {
    const float* x = (const float*)d_in[0];
    float* out = (float*)d_out;

    cudaFuncSetAttribute(gemm_min_kernel,
                         cudaFuncAttributeMaxDynamicSharedMemorySize, SMEM_TOTAL);

    normalize_kernel<<<B_ROWS / 8, 256>>>(x);
    gemm_min_kernel<<<dim3(NT, NT), 256, SMEM_TOTAL>>>();
    finalize1_kernel<<<32, 256>>>();
    finalize2_kernel<<<1, 32>>>(out);
}